// round 6
// baseline (speedup 1.0000x reference)
#include <cuda_runtime.h>

#define Bn   4
#define Cc   64
#define CIc  32
#define HMc  128
#define HCc  64
#define NCc  4096      // HCc*HCc
#define SPLITS 8
#define TK   128

typedef unsigned long long u64;

__device__ __forceinline__ u64 fma2(u64 a, u64 b, u64 c) {
    u64 d;
    asm("fma.rn.f32x2 %0, %1, %2, %3;" : "=l"(d) : "l"(a), "l"(b), "l"(c));
    return d;
}
__device__ __forceinline__ u64 mul2(u64 a, u64 b) {
    u64 d;
    asm("mul.rn.f32x2 %0, %1, %2;" : "=l"(d) : "l"(a), "l"(b));
    return d;
}
__device__ __forceinline__ u64 add2(u64 a, u64 b) {
    u64 d;
    asm("add.rn.f32x2 %0, %1, %2;" : "=l"(d) : "l"(a), "l"(b));
    return d;
}
__device__ __forceinline__ u64 pk2(float x, float y) {
    u64 r;
    asm("mov.b64 %0, {%1, %2};" : "=l"(r) : "f"(x), "f"(y));
    return r;
}
__device__ __forceinline__ void upk2(u64 v, float& x, float& y) {
    asm("mov.b64 {%0, %1}, %2;" : "=f"(x), "=f"(y) : "l"(v));
}

// Scratch (device globals; no allocation allowed)
__device__ float g_Q[Bn*NCc*CIc];
__device__ float g_K[Bn*NCc*CIc];
__device__ float g_V[Bn*NCc*CIc];
__device__ float g_Pacc[Bn*SPLITS*NCc*CIc];
__device__ float g_Pl[Bn*SPLITS*NCc];
__device__ float g_vconv[Bn*Cc*NCc];
__device__ float g_stats[2*Cc];
__device__ float g_ss[2*Cc];

__global__ void zero_k() {
    if (threadIdx.x < 2*Cc) g_stats[threadIdx.x] = 0.f;
}

// g(cross) -> Q, theta(cross) -> K   (both stored [b*Nc+p][32], pixel-major rows)
__global__ void proj_cross_k(const float* __restrict__ cross,
                             const float* __restrict__ gw, const float* __restrict__ gb,
                             const float* __restrict__ tw, const float* __restrict__ tb) {
    __shared__ float swg[CIc*Cc];
    __shared__ float swt[CIc*Cc];
    int tid = threadIdx.x;
    for (int i = tid; i < CIc*Cc; i += 128) { swg[i] = gw[i]; swt[i] = tw[i]; }
    __syncthreads();
    int pix = blockIdx.x*128 + tid;
    int b = pix >> 12, p = pix & (NCc-1);
    float q[CIc], k[CIc];
    #pragma unroll
    for (int o = 0; o < CIc; o++) { q[o] = gb[o]; k[o] = tb[o]; }
    const float* cp = cross + (size_t)b*Cc*NCc + p;
    for (int c = 0; c < Cc; c++) {
        float v = cp[(size_t)c*NCc];
        #pragma unroll
        for (int o = 0; o < CIc; o++) { q[o] += swg[o*Cc+c]*v; k[o] += swt[o*Cc+c]*v; }
    }
    float* qo = g_Q + (size_t)pix*CIc;
    float* ko = g_K + (size_t)pix*CIc;
    #pragma unroll
    for (int o = 0; o < CIc; o++) { qo[o] = q[o]; ko[o] = k[o]; }
}

// phi(bilinear-downsample(main)) -> V.  128->64 align_corners=False == exact 2x2 mean.
__global__ void proj_main_k(const float* __restrict__ mainf,
                            const float* __restrict__ pw, const float* __restrict__ pb) {
    __shared__ float swp[CIc*Cc];
    int tid = threadIdx.x;
    for (int i = tid; i < CIc*Cc; i += 128) swp[i] = pw[i];
    __syncthreads();
    int pix = blockIdx.x*128 + tid;
    int b = pix >> 12, p = pix & (NCc-1);
    int i = p >> 6, j = p & 63;
    float a[CIc];
    #pragma unroll
    for (int o = 0; o < CIc; o++) a[o] = pb[o];
    const float* mp = mainf + (size_t)b*Cc*HMc*HMc + (2*i)*HMc + 2*j;
    for (int c = 0; c < Cc; c++) {
        const float* m = mp + (size_t)c*HMc*HMc;
        float v = 0.25f*(m[0] + m[1] + m[HMc] + m[HMc+1]);
        #pragma unroll
        for (int o = 0; o < CIc; o++) a[o] += swp[o*Cc+c]*v;
    }
    float* vo = g_V + (size_t)pix*CIc;
    #pragma unroll
    for (int o = 0; o < CIc; o++) vo[o] = a[o];
}

// Flash-style attention, unnormalized exp (logits small: no max needed),
// split-K over 8 key ranges. TWO queries per thread: one smem K/V read per key
// feeds both queries (halves L1/LDS traffic), 8 independent FMA2 dot chains.
__global__ void __launch_bounds__(128, 2) attn_k() {
    __shared__ float4 Ks[TK*8];
    __shared__ float4 Vs[TK*8];
    int tid = threadIdx.x;
    int b = blockIdx.z, s = blockIdx.y;
    int n0 = blockIdx.x*256 + tid;       // query A
    int n1 = n0 + 128;                   // query B

    float4 qaf[8], qbf[8];
    {
        const float4* qa4 = reinterpret_cast<const float4*>(g_Q + ((size_t)(b*NCc + n0))*CIc);
        const float4* qb4 = reinterpret_cast<const float4*>(g_Q + ((size_t)(b*NCc + n1))*CIc);
        #pragma unroll
        for (int u = 0; u < 8; u++) { qaf[u] = qa4[u]; qbf[u] = qb4[u]; }
    }
    u64* qa = reinterpret_cast<u64*>(qaf);   // 16 packed pairs
    u64* qb = reinterpret_cast<u64*>(qbf);

    float4 accA4[8], accB4[8];
    #pragma unroll
    for (int u = 0; u < 8; u++) {
        accA4[u] = make_float4(0.f,0.f,0.f,0.f);
        accB4[u] = make_float4(0.f,0.f,0.f,0.f);
    }
    u64* accA = reinterpret_cast<u64*>(accA4);
    u64* accB = reinterpret_cast<u64*>(accB4);
    float la = 0.f, lb = 0.f;

    int keybase = b*NCc + s*(NCc/SPLITS);
    for (int t = 0; t < (NCc/SPLITS)/TK; t++) {
        const float4* ksrc = reinterpret_cast<const float4*>(g_K + ((size_t)(keybase + t*TK))*CIc);
        const float4* vsrc = reinterpret_cast<const float4*>(g_V + ((size_t)(keybase + t*TK))*CIc);
        __syncthreads();
        #pragma unroll
        for (int idx = tid; idx < TK*8; idx += 128) { Ks[idx] = ksrc[idx]; Vs[idx] = vsrc[idx]; }
        __syncthreads();
        #pragma unroll 2
        for (int j = 0; j < TK; j++) {
            float4 kk[8], vv[8];
            #pragma unroll
            for (int u = 0; u < 8; u++) { kk[u] = Ks[j*8+u]; vv[u] = Vs[j*8+u]; }
            u64* kv = reinterpret_cast<u64*>(kk);
            u64* vp = reinterpret_cast<u64*>(vv);
            // 8 independent packed chains (4 per query), depth 4 each
            u64 a0 = mul2(qa[0], kv[0]);
            u64 a1 = mul2(qa[1], kv[1]);
            u64 a2 = mul2(qa[2], kv[2]);
            u64 a3 = mul2(qa[3], kv[3]);
            u64 b0 = mul2(qb[0], kv[0]);
            u64 b1 = mul2(qb[1], kv[1]);
            u64 b2 = mul2(qb[2], kv[2]);
            u64 b3 = mul2(qb[3], kv[3]);
            #pragma unroll
            for (int u = 4; u < 16; u += 4) {
                a0 = fma2(qa[u+0], kv[u+0], a0);
                a1 = fma2(qa[u+1], kv[u+1], a1);
                a2 = fma2(qa[u+2], kv[u+2], a2);
                a3 = fma2(qa[u+3], kv[u+3], a3);
                b0 = fma2(qb[u+0], kv[u+0], b0);
                b1 = fma2(qb[u+1], kv[u+1], b1);
                b2 = fma2(qb[u+2], kv[u+2], b2);
                b3 = fma2(qb[u+3], kv[u+3], b3);
            }
            a0 = add2(a0, a1); a2 = add2(a2, a3); a0 = add2(a0, a2);
            b0 = add2(b0, b1); b2 = add2(b2, b3); b0 = add2(b0, b2);
            float xa, ya, xb, yb;
            upk2(a0, xa, ya);
            upk2(b0, xb, yb);
            float ea = __expf(xa + ya);
            float eb = __expf(xb + yb);
            la += ea; lb += eb;
            u64 epa = pk2(ea, ea);
            u64 epb = pk2(eb, eb);
            #pragma unroll
            for (int u = 0; u < 16; u++) {
                accA[u] = fma2(epa, vp[u], accA[u]);
                accB[u] = fma2(epb, vp[u], accB[u]);
            }
        }
    }
    float4* poA = reinterpret_cast<float4*>(g_Pacc + ((size_t)((b*SPLITS+s)*NCc + n0))*CIc);
    float4* poB = reinterpret_cast<float4*>(g_Pacc + ((size_t)((b*SPLITS+s)*NCc + n1))*CIc);
    #pragma unroll
    for (int u = 0; u < 8; u++) { poA[u] = accA4[u]; poB[u] = accB4[u]; }
    g_Pl[(b*SPLITS+s)*NCc + n0] = la;
    g_Pl[(b*SPLITS+s)*NCc + n1] = lb;
}

// Reduce split-K partials, normalize, apply W (1x1 conv 32->64), stage for coalesced
// channel-major write, and accumulate BN batch statistics.
__global__ void reduce_conv_k(const float* __restrict__ ww, const float* __restrict__ wb) {
    __shared__ float sw[Cc*CIc];       // 8 KB
    __shared__ float stage[Cc*129];    // 33 KB, padded
    int tid = threadIdx.x;
    for (int i = tid; i < Cc*CIc; i += 128) sw[i] = ww[i];
    __syncthreads();
    int pix = blockIdx.x*128 + tid;
    int b = pix >> 12;
    int n = pix & (NCc-1);

    float4 acc[8];
    #pragma unroll
    for (int u = 0; u < 8; u++) acc[u] = make_float4(0.f,0.f,0.f,0.f);
    float l = 0.f;
    for (int s = 0; s < SPLITS; s++) {
        const float4* pa = reinterpret_cast<const float4*>(
            g_Pacc + ((size_t)((b*SPLITS+s)*NCc + n))*CIc);
        #pragma unroll
        for (int u = 0; u < 8; u++) {
            float4 v = pa[u];
            acc[u].x += v.x; acc[u].y += v.y; acc[u].z += v.z; acc[u].w += v.w;
        }
        l += g_Pl[(b*SPLITS+s)*NCc + n];
    }
    float inv = 1.f/l;
    float a[CIc];
    #pragma unroll
    for (int u = 0; u < 8; u++) {
        a[4*u+0] = acc[u].x*inv; a[4*u+1] = acc[u].y*inv;
        a[4*u+2] = acc[u].z*inv; a[4*u+3] = acc[u].w*inv;
    }
    for (int o = 0; o < Cc; o++) {
        float t = wb[o];
        #pragma unroll
        for (int c = 0; c < CIc; c++) t += sw[o*CIc+c]*a[c];
        stage[o*129 + tid] = t;
    }
    __syncthreads();
    int pblock = (blockIdx.x*128) & (NCc-1);
    float* vout = g_vconv + (size_t)b*Cc*NCc + pblock;
    for (int idx = tid; idx < Cc*128; idx += 128) {
        int o = idx >> 7, pl = idx & 127;
        vout[(size_t)o*NCc + pl] = stage[o*129 + pl];
    }
    if (tid < Cc) {
        float s1 = 0.f, s2 = 0.f;
        for (int pl = 0; pl < 128; pl++) {
            float v = stage[tid*129 + pl];
            s1 += v; s2 += v*v;
        }
        atomicAdd(&g_stats[tid], s1);
        atomicAdd(&g_stats[Cc+tid], s2);
    }
}

__global__ void finalize_k(const float* __restrict__ gamma, const float* __restrict__ beta) {
    int o = threadIdx.x;
    if (o < Cc) {
        float ninv = 1.f/(float)(Bn*NCc);
        float mean = g_stats[o]*ninv;
        float var  = g_stats[Cc+o]*ninv - mean*mean;
        float sc   = gamma[o]*rsqrtf(var + 1e-5f);
        g_ss[o]    = sc;
        g_ss[Cc+o] = beta[o] - mean*sc;
    }
}

// BN is per-channel affine and bilerp weights sum to 1, so normalize during upsample:
// out = sc*bilerp(vconv) + sh + main
__global__ void upsample_k(const float* __restrict__ mainf, float* __restrict__ out) {
    int idx = blockIdx.x*256 + threadIdx.x;
    int j = idx & 127, i = (idx >> 7) & 127, o = (idx >> 14) & 63, b = idx >> 20;
    float si = fminf(fmaxf((i+0.5f)*0.5f - 0.5f, 0.f), 63.f);
    float sj = fminf(fmaxf((j+0.5f)*0.5f - 0.5f, 0.f), 63.f);
    int i0 = (int)si; int i1 = min(i0+1, 63); float wi = si - (float)i0;
    int j0 = (int)sj; int j1 = min(j0+1, 63); float wj = sj - (float)j0;
    const float* vb = g_vconv + ((size_t)(b*Cc + o))*NCc;
    float v00 = vb[i0*64 + j0], v01 = vb[i0*64 + j1];
    float v10 = vb[i1*64 + j0], v11 = vb[i1*64 + j1];
    float v = (v00*(1.f-wj) + v01*wj)*(1.f-wi) + (v10*(1.f-wj) + v11*wj)*wi;
    out[idx] = v*g_ss[o] + g_ss[Cc+o] + mainf[idx];
}

extern "C" void kernel_launch(void* const* d_in, const int* in_sizes, int n_in,
                              void* d_out, int out_size) {
    const float* mainf   = (const float*)d_in[0];
    const float* crossf  = (const float*)d_in[1];
    const float* g_w     = (const float*)d_in[2];
    const float* g_b     = (const float*)d_in[3];
    const float* theta_w = (const float*)d_in[4];
    const float* theta_b = (const float*)d_in[5];
    const float* phi_w   = (const float*)d_in[6];
    const float* phi_b   = (const float*)d_in[7];
    const float* w_w     = (const float*)d_in[8];
    const float* w_b     = (const float*)d_in[9];
    const float* bn_g    = (const float*)d_in[10];
    const float* bn_b    = (const float*)d_in[11];
    float* out = (float*)d_out;

    zero_k<<<1, 128>>>();
    proj_cross_k<<<Bn*NCc/128, 128>>>(crossf, g_w, g_b, theta_w, theta_b);
    proj_main_k<<<Bn*NCc/128, 128>>>(mainf, phi_w, phi_b);
    attn_k<<<dim3(NCc/256, SPLITS, Bn), 128>>>();
    reduce_conv_k<<<Bn*NCc/128, 128>>>(w_w, w_b);
    finalize_k<<<1, 64>>>(bn_g, bn_b);
    upsample_k<<<(Bn*Cc*HMc*HMc)/256, 256>>>(mainf, out);
}

// round 8
// speedup vs baseline: 2.3363x; 2.3363x over previous
#include <cuda_runtime.h>
#include <cstdint>

#define Bn   4
#define Cc   64
#define CIc  32
#define HMc  128
#define NCc  4096

// ---------------- helpers ----------------------------------------------------
__device__ __forceinline__ float tf32r(float x) {
    unsigned u; asm("cvt.rna.tf32.f32 %0, %1;" : "=r"(u) : "f"(x));
    return __uint_as_float(u);
}
// D += A*B, m16n8k8 tf32 (A row-major, B col-major)
__device__ __forceinline__ void mma_tf32(float* d, const unsigned* a, const unsigned* b) {
    asm volatile("mma.sync.aligned.m16n8k8.row.col.f32.tf32.tf32.f32 "
        "{%0,%1,%2,%3}, {%4,%5,%6,%7}, {%8,%9}, {%0,%1,%2,%3};"
        : "+f"(d[0]), "+f"(d[1]), "+f"(d[2]), "+f"(d[3])
        : "r"(a[0]), "r"(a[1]), "r"(a[2]), "r"(a[3]), "r"(b[0]), "r"(b[1]));
}

// ---------------- scratch globals (no allocation allowed) --------------------
__device__ float g_Q[Bn*NCc*CIc];
__device__ float g_K[Bn*NCc*CIc];
__device__ float g_V[Bn*NCc*CIc];
__device__ float g_attn[Bn*NCc*CIc];   // normalized attention output, [pix][32]
__device__ float g_vconv[Bn*Cc*NCc];
__device__ float g_stats[2*Cc];
__device__ float g_ss[2*Cc];

__global__ void zero_k() {
    if (threadIdx.x < 2*Cc) g_stats[threadIdx.x] = 0.f;
}

// g(cross) -> Q, theta(cross) -> K  (tf32-rounded, [b*Nc+p][32] rows)
__global__ void proj_cross_k(const float* __restrict__ cross,
                             const float* __restrict__ gw, const float* __restrict__ gb,
                             const float* __restrict__ tw, const float* __restrict__ tb) {
    __shared__ float swg[CIc*Cc];
    __shared__ float swt[CIc*Cc];
    int tid = threadIdx.x;
    for (int i = tid; i < CIc*Cc; i += 128) { swg[i] = gw[i]; swt[i] = tw[i]; }
    __syncthreads();
    int pix = blockIdx.x*128 + tid;
    int b = pix >> 12, p = pix & (NCc-1);
    float q[CIc], k[CIc];
    #pragma unroll
    for (int o = 0; o < CIc; o++) { q[o] = gb[o]; k[o] = tb[o]; }
    const float* cp = cross + (size_t)b*Cc*NCc + p;
    for (int c = 0; c < Cc; c++) {
        float v = cp[(size_t)c*NCc];
        #pragma unroll
        for (int o = 0; o < CIc; o++) { q[o] += swg[o*Cc+c]*v; k[o] += swt[o*Cc+c]*v; }
    }
    float* qo = g_Q + (size_t)pix*CIc;
    float* ko = g_K + (size_t)pix*CIc;
    #pragma unroll
    for (int o = 0; o < CIc; o++) { qo[o] = tf32r(q[o]); ko[o] = tf32r(k[o]); }
}

// phi(bilinear-downsample(main)) -> V (tf32-rounded, pixel-major rows of 32).
__global__ void proj_main_k(const float* __restrict__ mainf,
                            const float* __restrict__ pw, const float* __restrict__ pb) {
    __shared__ float swp[CIc*Cc];
    int tid = threadIdx.x;
    for (int i = tid; i < CIc*Cc; i += 128) swp[i] = pw[i];
    __syncthreads();
    int pix = blockIdx.x*128 + tid;
    int b = pix >> 12, p = pix & (NCc-1);
    int i = p >> 6, j = p & 63;
    float a[CIc];
    #pragma unroll
    for (int o = 0; o < CIc; o++) a[o] = pb[o];
    const float* mp = mainf + (size_t)b*Cc*HMc*HMc + (2*i)*HMc + 2*j;
    for (int c = 0; c < Cc; c++) {
        const float* m = mp + (size_t)c*HMc*HMc;
        float v = 0.25f*(m[0] + m[1] + m[HMc] + m[HMc+1]);
        #pragma unroll
        for (int o = 0; o < CIc; o++) a[o] += swp[o*Cc+c]*v;
    }
    float* vo = g_V + (size_t)pix*CIc;
    #pragma unroll
    for (int o = 0; o < CIc; o++) vo[o] = tf32r(a[o]);
}

// ---------------- tensor-core attention (mma.sync tf32) ----------------------
// CTA = 128-query tile x batch, 8 warps x 16-row strips. Per 128-key tile:
//   S = Q@K^T (mma), P = exp(S) (regs), P round-trip via warp-private smem,
//   O += P@V (mma). Unnormalized accumulation across ALL key tiles (logits are
//   O(1): no max subtraction needed), l summed per row, normalize at the end.
// smem word-offset layout (fragment-paired, conflict-free strides):
#define KSTR 40
#define VSTR 72
#define PSTR 132
#define SM_K 0
#define SM_V (128*KSTR)                 // 5120
#define SM_P (SM_V + 64*VSTR)           // 9728
#define ATTN_SMEM ((SM_P + 128*PSTR)*4) // 106496 bytes

__global__ void __launch_bounds__(256, 1) attn_tc_k() {
    extern __shared__ float sm[];
    int tid = threadIdx.x, lane = tid & 31, w = tid >> 5;
    int gq = lane >> 2, gj = lane & 3;
    int b = blockIdx.y, qbase = blockIdx.x*128;

    // Q fragments: rows 16w+gq, 16w+gq+8; 4 k-chunks of 8
    unsigned qa[4][4];
    {
        const float* Qb = g_Q + ((size_t)(b*NCc + qbase + 16*w))*CIc;
        #pragma unroll
        for (int kc = 0; kc < 4; kc++) {
            qa[kc][0] = __float_as_uint(Qb[gq*32     + 8*kc + gj]);
            qa[kc][1] = __float_as_uint(Qb[(gq+8)*32 + 8*kc + gj]);
            qa[kc][2] = __float_as_uint(Qb[gq*32     + 8*kc + gj + 4]);
            qa[kc][3] = __float_as_uint(Qb[(gq+8)*32 + 8*kc + gj + 4]);
        }
    }

    float O[4][4];
    #pragma unroll
    for (int n = 0; n < 4; n++) { O[n][0]=O[n][1]=O[n][2]=O[n][3]=0.f; }
    float la = 0.f, lb = 0.f;

    int r = tid >> 1, h2 = tid & 1;   // fill: key row r, column half h2
    for (int t = 0; t < 32; t++) {
        __syncthreads();   // previous tile fully consumed
        // K tile -> fragment-paired layout: K'[key][kc*8 + (c&3)*2 + (c>>2 within chunk)]
        {
            const float4* ks = reinterpret_cast<const float4*>(
                g_K + ((size_t)(b*NCc + t*128 + r))*CIc + h2*16);
            #pragma unroll
            for (int i = 0; i < 4; i++) {
                float4 v4 = ks[i];
                float vv[4] = {v4.x, v4.y, v4.z, v4.w};
                #pragma unroll
                for (int u = 0; u < 4; u++) {
                    int c = h2*16 + 4*i + u;
                    sm[SM_K + r*KSTR + (c>>3)*8 + (c&3)*2 + ((c&7)>>2)] = vv[u];
                }
            }
        }
        // V tile -> key-paired layout: V'[(kc*4+gj)][ch*2 + (key&7)>>2]
        {
            const float4* vs = reinterpret_cast<const float4*>(
                g_V + ((size_t)(b*NCc + t*128 + r))*CIc + h2*16);
            int base = SM_V + ((r>>3)*4 + (r&3))*VSTR + ((r&7)>>2);
            #pragma unroll
            for (int i = 0; i < 4; i++) {
                float4 v4 = vs[i];
                int c0 = h2*16 + 4*i;
                sm[base + (c0+0)*2] = v4.x;
                sm[base + (c0+1)*2] = v4.y;
                sm[base + (c0+2)*2] = v4.z;
                sm[base + (c0+3)*2] = v4.w;
            }
        }
        __syncthreads();

        // QK: 16 n-tiles of 8 keys, k = 32 (4 chunks)
        float S[16][4];
        #pragma unroll
        for (int n = 0; n < 16; n++) {
            S[n][0]=S[n][1]=S[n][2]=S[n][3]=0.f;
            const float* kr = sm + SM_K + (8*n + gq)*KSTR + gj*2;
            #pragma unroll
            for (int kc = 0; kc < 4; kc++) {
                uint2 kb = *reinterpret_cast<const uint2*>(kr + kc*8);
                unsigned bb[2] = {kb.x, kb.y};
                mma_tf32(S[n], qa[kc], bb);
            }
        }
        // exp + warp-private P store
        #pragma unroll
        for (int n = 0; n < 16; n++) {
            float e0 = __expf(S[n][0]), e1 = __expf(S[n][1]);
            float e2 = __expf(S[n][2]), e3 = __expf(S[n][3]);
            la += e0 + e1; lb += e2 + e3;
            int col = 8*n + 2*gj;
            *reinterpret_cast<float2*>(sm + SM_P + (16*w+gq)*PSTR + col) =
                make_float2(tf32r(e0), tf32r(e1));
            *reinterpret_cast<float2*>(sm + SM_P + (16*w+gq+8)*PSTR + col) =
                make_float2(tf32r(e2), tf32r(e3));
        }
        __syncwarp();
        // PV: O[16x32] += P[16x128] @ V[128x32]
        const float* Pr0 = sm + SM_P + (16*w+gq)*PSTR + gj;
        #pragma unroll
        for (int kc = 0; kc < 16; kc++) {
            unsigned pa[4];
            pa[0] = __float_as_uint(Pr0[kc*8]);
            pa[1] = __float_as_uint(Pr0[8*PSTR + kc*8]);
            pa[2] = __float_as_uint(Pr0[kc*8 + 4]);
            pa[3] = __float_as_uint(Pr0[8*PSTR + kc*8 + 4]);
            const float* vr = sm + SM_V + (kc*4+gj)*VSTR + gq*2;
            #pragma unroll
            for (int n = 0; n < 4; n++) {
                uint2 vb = *reinterpret_cast<const uint2*>(vr + 16*n);
                unsigned bb[2] = {vb.x, vb.y};
                mma_tf32(O[n], pa, bb);
            }
        }
    }
    // row sums: reduce over the 4 lanes of each quad
    la += __shfl_xor_sync(0xffffffffu, la, 1);
    la += __shfl_xor_sync(0xffffffffu, la, 2);
    lb += __shfl_xor_sync(0xffffffffu, lb, 1);
    lb += __shfl_xor_sync(0xffffffffu, lb, 2);
    float ia = 1.f/la, ib = 1.f/lb;
    int row0 = qbase + 16*w + gq;
    float* dst = g_attn + ((size_t)b*NCc)*CIc;
    #pragma unroll
    for (int n = 0; n < 4; n++) {
        int col = 8*n + 2*gj;
        *reinterpret_cast<float2*>(dst + (size_t)row0*32 + col) =
            make_float2(O[n][0]*ia, O[n][1]*ia);
        *reinterpret_cast<float2*>(dst + (size_t)(row0+8)*32 + col) =
            make_float2(O[n][2]*ib, O[n][3]*ib);
    }
}

// Apply W (1x1 conv 32->64), coalesced channel-major write, BN batch stats.
__global__ void reduce_conv_k(const float* __restrict__ ww, const float* __restrict__ wb) {
    __shared__ float sw[Cc*CIc];
    __shared__ float stage[Cc*129];
    int tid = threadIdx.x;
    for (int i = tid; i < Cc*CIc; i += 128) sw[i] = ww[i];
    __syncthreads();
    int pix = blockIdx.x*128 + tid;
    int b = pix >> 12;

    float a[CIc];
    {
        const float4* pa = reinterpret_cast<const float4*>(g_attn + (size_t)pix*CIc);
        #pragma unroll
        for (int u = 0; u < 8; u++) {
            float4 v = pa[u];
            a[4*u+0] = v.x; a[4*u+1] = v.y; a[4*u+2] = v.z; a[4*u+3] = v.w;
        }
    }
    for (int o = 0; o < Cc; o++) {
        float t = wb[o];
        #pragma unroll
        for (int c = 0; c < CIc; c++) t += sw[o*CIc+c]*a[c];
        stage[o*129 + tid] = t;
    }
    __syncthreads();
    int pblock = (blockIdx.x*128) & (NCc-1);
    float* vout = g_vconv + (size_t)b*Cc*NCc + pblock;
    for (int idx = tid; idx < Cc*128; idx += 128) {
        int o = idx >> 7, pl = idx & 127;
        vout[(size_t)o*NCc + pl] = stage[o*129 + pl];
    }
    if (tid < Cc) {
        float s1 = 0.f, s2 = 0.f;
        for (int pl = 0; pl < 128; pl++) {
            float v = stage[tid*129 + pl];
            s1 += v; s2 += v*v;
        }
        atomicAdd(&g_stats[tid], s1);
        atomicAdd(&g_stats[Cc+tid], s2);
    }
}

__global__ void finalize_k(const float* __restrict__ gamma, const float* __restrict__ beta) {
    int o = threadIdx.x;
    if (o < Cc) {
        float ninv = 1.f/(float)(Bn*NCc);
        float mean = g_stats[o]*ninv;
        float var  = g_stats[Cc+o]*ninv - mean*mean;
        float sc   = gamma[o]*rsqrtf(var + 1e-5f);
        g_ss[o]    = sc;
        g_ss[Cc+o] = beta[o] - mean*sc;
    }
}

// BN folded into upsample: out = sc*bilerp(vconv) + sh + main
__global__ void upsample_k(const float* __restrict__ mainf, float* __restrict__ out) {
    int idx = blockIdx.x*256 + threadIdx.x;
    int j = idx & 127, i = (idx >> 7) & 127, o = (idx >> 14) & 63, b = idx >> 20;
    float si = fminf(fmaxf((i+0.5f)*0.5f - 0.5f, 0.f), 63.f);
    float sj = fminf(fmaxf((j+0.5f)*0.5f - 0.5f, 0.f), 63.f);
    int i0 = (int)si; int i1 = min(i0+1, 63); float wi = si - (float)i0;
    int j0 = (int)sj; int j1 = min(j0+1, 63); float wj = sj - (float)j0;
    const float* vb = g_vconv + ((size_t)(b*Cc + o))*NCc;
    float v00 = vb[i0*64 + j0], v01 = vb[i0*64 + j1];
    float v10 = vb[i1*64 + j0], v11 = vb[i1*64 + j1];
    float v = (v00*(1.f-wj) + v01*wj)*(1.f-wi) + (v10*(1.f-wj) + v11*wj)*wi;
    out[idx] = v*g_ss[o] + g_ss[Cc+o] + mainf[idx];
}

extern "C" void kernel_launch(void* const* d_in, const int* in_sizes, int n_in,
                              void* d_out, int out_size) {
    const float* mainf   = (const float*)d_in[0];
    const float* crossf  = (const float*)d_in[1];
    const float* g_w     = (const float*)d_in[2];
    const float* g_b     = (const float*)d_in[3];
    const float* theta_w = (const float*)d_in[4];
    const float* theta_b = (const float*)d_in[5];
    const float* phi_w   = (const float*)d_in[6];
    const float* phi_b   = (const float*)d_in[7];
    const float* w_w     = (const float*)d_in[8];
    const float* w_b     = (const float*)d_in[9];
    const float* bn_g    = (const float*)d_in[10];
    const float* bn_b    = (const float*)d_in[11];
    float* out = (float*)d_out;

    cudaFuncSetAttribute(attn_tc_k, cudaFuncAttributeMaxDynamicSharedMemorySize, ATTN_SMEM);

    zero_k<<<1, 128>>>();
    proj_cross_k<<<Bn*NCc/128, 128>>>(crossf, g_w, g_b, theta_w, theta_b);
    proj_main_k<<<Bn*NCc/128, 128>>>(mainf, phi_w, phi_b);
    attn_tc_k<<<dim3(NCc/128, Bn), 256, ATTN_SMEM>>>();
    reduce_conv_k<<<Bn*NCc/128, 128>>>(w_w, w_b);
    finalize_k<<<1, 64>>>(bn_g, bn_b);
    upsample_k<<<(Bn*Cc*HMc*HMc)/256, 256>>>(mainf, out);
}